// round 2
// baseline (speedup 1.0000x reference)
#include <cuda_runtime.h>
#include <cuda_bf16.h>

#define TPB   256
#define GRID  1036            // 148 SMs * 7 CTAs (32KB smem each)
#define NQ    10
#define EPSF  1e-12f
#define L2E   1.4426950408889634f
#define MAXPTS 2048

__device__ float2 g_partials[GRID];

__global__ __launch_bounds__(TPB) void cvm_partial_kernel(
    const float* __restrict__ z0, const float* __restrict__ v0,
    const float* __restrict__ beta_p, const float* __restrict__ data_t,
    const float* __restrict__ t0_p, const float* __restrict__ tn_p,
    const int2* __restrict__ data_uv,
    const int* __restrict__ pair_u, const int* __restrict__ pair_v,
    int n_points, int n_events, int n_pairs)
{
    __shared__ float4 sm[MAXPTS];
    const float2* z2 = (const float2*)z0;
    const float2* v2 = (const float2*)v0;
    for (int i = threadIdx.x; i < n_points; i += TPB) {
        float2 z = z2[i];
        float2 v = v2[i];
        sm[i] = make_float4(z.x, z.y, v.x, v.y);
    }
    __syncthreads();

    const float beta = *beta_p;
    const float t0   = *t0_p;
    const float tn   = *tn_p;
    const float dtq  = (tn - t0) * (1.0f / NQ);
    const float bL2E = beta * L2E;

    float acc_d = 0.0f;   // sum of event distances
    float acc_e = 0.0f;   // sum of exp(beta - pair dist) over pairs x quad

    const int stride = GRID * TPB;
    const int tid    = blockIdx.x * TPB + threadIdx.x;

    // ---- event term: memory-streaming, 1 MUFU per event ----
    for (int i = tid; i < n_events; i += stride) {
        int2  uv = data_uv[i];
        float t  = data_t[i];
        float4 a = sm[uv.x];
        float4 b = sm[uv.y];
        float dx = fmaf(a.z - b.z, t, a.x - b.x);
        float dy = fmaf(a.w - b.w, t, a.y - b.y);
        float s  = fmaf(dx, dx, fmaf(dy, dy, EPSF));
        float d;  asm("sqrt.approx.f32 %0, %1;" : "=f"(d) : "f"(s));
        acc_d += d;
    }

    // ---- pair term: MUFU-bound (SQRT + EX2 per quad point) ----
    for (int i = tid; i < n_pairs; i += stride) {
        int u = pair_u[i];
        int v = pair_v[i];
        float4 a = sm[u];
        float4 b = sm[v];
        float dx0 = a.x - b.x;
        float dy0 = a.y - b.y;
        float dvx = a.z - b.z;
        float dvy = a.w - b.w;
        #pragma unroll
        for (int k = 0; k < NQ; k++) {
            float tk = t0 + ((float)k + 0.5f) * dtq;
            float dx = fmaf(dvx, tk, dx0);
            float dy = fmaf(dvy, tk, dy0);
            float s  = fmaf(dx, dx, fmaf(dy, dy, EPSF));
            float d;   asm("sqrt.approx.f32 %0, %1;" : "=f"(d) : "f"(s));
            float arg = fmaf(d, -L2E, bL2E);
            float e;   asm("ex2.approx.f32 %0, %1;" : "=f"(e) : "f"(arg));
            acc_e += e;
        }
    }

    // ---- warp reduce, then block reduce ----
    #pragma unroll
    for (int o = 16; o > 0; o >>= 1) {
        acc_d += __shfl_down_sync(0xffffffffu, acc_d, o);
        acc_e += __shfl_down_sync(0xffffffffu, acc_e, o);
    }
    __shared__ float2 wred[TPB / 32];
    if ((threadIdx.x & 31) == 0)
        wred[threadIdx.x >> 5] = make_float2(acc_d, acc_e);
    __syncthreads();
    if (threadIdx.x == 0) {
        float sd = 0.0f, se = 0.0f;
        #pragma unroll
        for (int w = 0; w < TPB / 32; w++) { sd += wred[w].x; se += wred[w].y; }
        g_partials[blockIdx.x] = make_float2(sd, se);
    }
}

__global__ __launch_bounds__(256) void cvm_final_kernel(
    const float* __restrict__ beta_p, const float* __restrict__ t0_p,
    const float* __restrict__ tn_p, int n_events, float* __restrict__ out)
{
    double sd = 0.0, se = 0.0;
    for (int i = threadIdx.x; i < GRID; i += 256) {
        float2 p = g_partials[i];
        sd += (double)p.x;
        se += (double)p.y;
    }
    #pragma unroll
    for (int o = 16; o > 0; o >>= 1) {
        sd += __shfl_down_sync(0xffffffffu, sd, o);
        se += __shfl_down_sync(0xffffffffu, se, o);
    }
    __shared__ double2 wred[8];
    if ((threadIdx.x & 31) == 0)
        wred[threadIdx.x >> 5] = make_double2(sd, se);
    __syncthreads();
    if (threadIdx.x == 0) {
        double tsd = 0.0, tse = 0.0;
        #pragma unroll
        for (int w = 0; w < 8; w++) { tsd += wred[w].x; tse += wred[w].y; }
        double beta = (double)(*beta_p);
        double dtq  = ((double)(*tn_p) - (double)(*t0_p)) / (double)NQ;
        // event_intensity = beta*NE - sum(d); non_event = dtq * sum(exp)
        double result = beta * (double)n_events - tsd - 1.0 /*NON_EVENT_WEIGHT*/ * dtq * tse;
        out[0] = (float)result;
    }
}

extern "C" void kernel_launch(void* const* d_in, const int* in_sizes, int n_in,
                              void* d_out, int out_size)
{
    // metadata order: z0, v0, beta, data_t, t0, tn, data_uv, pair_u, pair_v
    const float* z0      = (const float*)d_in[0];
    const float* v0      = (const float*)d_in[1];
    const float* beta_p  = (const float*)d_in[2];
    const float* data_t  = (const float*)d_in[3];
    const float* t0_p    = (const float*)d_in[4];
    const float* tn_p    = (const float*)d_in[5];
    const int2*  data_uv = (const int2*)d_in[6];
    const int*   pair_u  = (const int*)d_in[7];
    const int*   pair_v  = (const int*)d_in[8];
    float* out = (float*)d_out;

    int n_points = in_sizes[0] / 2;
    int n_events = in_sizes[3];
    int n_pairs  = in_sizes[7];

    cvm_partial_kernel<<<GRID, TPB>>>(z0, v0, beta_p, data_t, t0_p, tn_p,
                                      data_uv, pair_u, pair_v,
                                      n_points, n_events, n_pairs);
    cvm_final_kernel<<<1, 256>>>(beta_p, t0_p, tn_p, n_events, out);
}

// round 3
// speedup vs baseline: 1.1616x; 1.1616x over previous
#include <cuda_runtime.h>
#include <cuda_bf16.h>

#define TPB    256
#define NBLK   592             // 148 SMs * 4 CTAs (forced by launch_bounds)
#define NQ     10
#define EPSF   1e-12f
#define L2E    1.4426950408889634f
#define MAXPTS 2048

__device__ float2       g_partials[NBLK];
__device__ unsigned int g_sem = 0;   // self-resetting via atomicInc wrap

__device__ __forceinline__ float fsqrt_approx(float s) {
    float d; asm("sqrt.approx.f32 %0, %1;" : "=f"(d) : "f"(s)); return d;
}
__device__ __forceinline__ float fex2_approx(float a) {
    float e; asm("ex2.approx.f32 %0, %1;" : "=f"(e) : "f"(a)); return e;
}

__global__ __launch_bounds__(TPB, 4) void cvm_fused_kernel(
    const float* __restrict__ z0, const float* __restrict__ v0,
    const float* __restrict__ beta_p, const float* __restrict__ data_t,
    const float* __restrict__ t0_p, const float* __restrict__ tn_p,
    const int2* __restrict__ data_uv,
    const int* __restrict__ pair_u, const int* __restrict__ pair_v,
    int n_points, int n_events, int n_pairs,
    float* __restrict__ out)
{
    __shared__ float4 sm[MAXPTS];
    {
        const float2* z2 = (const float2*)z0;
        const float2* v2 = (const float2*)v0;
        for (int i = threadIdx.x; i < n_points; i += TPB) {
            float2 z = z2[i];
            float2 v = v2[i];
            sm[i] = make_float4(z.x, z.y, v.x, v.y);
        }
    }
    __syncthreads();

    const float beta = *beta_p;
    const float t0   = *t0_p;
    const float tn   = *tn_p;
    const float dtq  = (tn - t0) * (1.0f / NQ);
    const float bL2E = beta * L2E;

    // quadrature abscissae as registers (compile-time unrolled)
    float ts[NQ];
    #pragma unroll
    for (int k = 0; k < NQ; k++) ts[k] = t0 + ((float)k + 0.5f) * dtq;

    float acc_d  = 0.0f;
    float acc_e0 = 0.0f, acc_e1 = 0.0f;

    const int stride = NBLK * TPB;
    const int tid    = blockIdx.x * TPB + threadIdx.x;

    // ---- event term: 2 events / iter (int4 + float2 loads) ----
    {
        const int4*   uv4 = (const int4*)data_uv;
        const float2* tt2 = (const float2*)data_t;
        const int nev2 = n_events >> 1;
        for (int i = tid; i < nev2; i += stride) {
            int4   q  = uv4[i];
            float2 tt = tt2[i];
            float4 a0 = sm[q.x], b0 = sm[q.y];
            float4 a1 = sm[q.z], b1 = sm[q.w];
            float dx0 = fmaf(a0.z - b0.z, tt.x, a0.x - b0.x);
            float dy0 = fmaf(a0.w - b0.w, tt.x, a0.y - b0.y);
            float dx1 = fmaf(a1.z - b1.z, tt.y, a1.x - b1.x);
            float dy1 = fmaf(a1.w - b1.w, tt.y, a1.y - b1.y);
            float s0 = fmaf(dx0, dx0, fmaf(dy0, dy0, EPSF));
            float s1 = fmaf(dx1, dx1, fmaf(dy1, dy1, EPSF));
            acc_d += fsqrt_approx(s0);
            acc_d += fsqrt_approx(s1);
        }
        // odd remainder (n_events even in practice; keep generic)
        if ((n_events & 1) && tid == 0) {
            int   i = n_events - 1;
            int2  uv = data_uv[i];
            float t  = data_t[i];
            float4 a = sm[uv.x], b = sm[uv.y];
            float dx = fmaf(a.z - b.z, t, a.x - b.x);
            float dy = fmaf(a.w - b.w, t, a.y - b.y);
            acc_d += fsqrt_approx(fmaf(dx, dx, fmaf(dy, dy, EPSF)));
        }
    }

    // ---- pair term: 2 pairs / iter, 10 quad points each ----
    {
        const int2* pu2 = (const int2*)pair_u;
        const int2* pv2 = (const int2*)pair_v;
        const int np2 = n_pairs >> 1;
        for (int i = tid; i < np2; i += stride) {
            int2 uu = pu2[i];
            int2 vv = pv2[i];
            float4 a0 = sm[uu.x], b0 = sm[vv.x];
            float4 a1 = sm[uu.y], b1 = sm[vv.y];
            float dx0 = a0.x - b0.x, dy0 = a0.y - b0.y;
            float vx0 = a0.z - b0.z, vy0 = a0.w - b0.w;
            float dx1 = a1.x - b1.x, dy1 = a1.y - b1.y;
            float vx1 = a1.z - b1.z, vy1 = a1.w - b1.w;
            #pragma unroll
            for (int k = 0; k < NQ; k++) {
                float tk = ts[k];
                float ex0 = fmaf(vx0, tk, dx0);
                float ey0 = fmaf(vy0, tk, dy0);
                float ex1 = fmaf(vx1, tk, dx1);
                float ey1 = fmaf(vy1, tk, dy1);
                float s0  = fmaf(ex0, ex0, fmaf(ey0, ey0, EPSF));
                float s1  = fmaf(ex1, ex1, fmaf(ey1, ey1, EPSF));
                float d0  = fsqrt_approx(s0);
                float d1  = fsqrt_approx(s1);
                acc_e0 += fex2_approx(fmaf(d0, -L2E, bL2E));
                acc_e1 += fex2_approx(fmaf(d1, -L2E, bL2E));
            }
        }
        if ((n_pairs & 1) && tid == 0) {
            int i = n_pairs - 1;
            float4 a = sm[pair_u[i]], b = sm[pair_v[i]];
            float dx0 = a.x - b.x, dy0 = a.y - b.y;
            float vx0 = a.z - b.z, vy0 = a.w - b.w;
            #pragma unroll
            for (int k = 0; k < NQ; k++) {
                float ex = fmaf(vx0, ts[k], dx0);
                float ey = fmaf(vy0, ts[k], dy0);
                float d  = fsqrt_approx(fmaf(ex, ex, fmaf(ey, ey, EPSF)));
                acc_e0 += fex2_approx(fmaf(d, -L2E, bL2E));
            }
        }
    }

    float acc_e = acc_e0 + acc_e1;

    // ---- intra-block reduce ----
    #pragma unroll
    for (int o = 16; o > 0; o >>= 1) {
        acc_d += __shfl_down_sync(0xffffffffu, acc_d, o);
        acc_e += __shfl_down_sync(0xffffffffu, acc_e, o);
    }
    __shared__ float2 wred[TPB / 32];
    if ((threadIdx.x & 31) == 0)
        wred[threadIdx.x >> 5] = make_float2(acc_d, acc_e);
    __syncthreads();

    __shared__ bool is_last;
    if (threadIdx.x == 0) {
        float sd = 0.0f, se = 0.0f;
        #pragma unroll
        for (int w = 0; w < TPB / 32; w++) { sd += wred[w].x; se += wred[w].y; }
        g_partials[blockIdx.x] = make_float2(sd, se);
        __threadfence();
        unsigned old = atomicInc(&g_sem, NBLK - 1);  // wraps to 0 after NBLK calls
        is_last = (old == NBLK - 1);
    }
    __syncthreads();

    // ---- last block: deterministic final reduce (double) ----
    if (is_last) {
        double sd = 0.0, se = 0.0;
        const volatile float2* gp = (const volatile float2*)g_partials;
        for (int i = threadIdx.x; i < NBLK; i += TPB) {
            sd += (double)gp[i].x;
            se += (double)gp[i].y;
        }
        #pragma unroll
        for (int o = 16; o > 0; o >>= 1) {
            sd += __shfl_down_sync(0xffffffffu, sd, o);
            se += __shfl_down_sync(0xffffffffu, se, o);
        }
        __shared__ double2 dred[TPB / 32];
        if ((threadIdx.x & 31) == 0)
            dred[threadIdx.x >> 5] = make_double2(sd, se);
        __syncthreads();
        if (threadIdx.x == 0) {
            double tsd = 0.0, tse = 0.0;
            #pragma unroll
            for (int w = 0; w < TPB / 32; w++) { tsd += dred[w].x; tse += dred[w].y; }
            double betaD = (double)beta;
            double dtqD  = ((double)tn - (double)t0) / (double)NQ;
            out[0] = (float)(betaD * (double)n_events - tsd - dtqD * tse);
        }
    }
}

extern "C" void kernel_launch(void* const* d_in, const int* in_sizes, int n_in,
                              void* d_out, int out_size)
{
    // metadata order: z0, v0, beta, data_t, t0, tn, data_uv, pair_u, pair_v
    const float* z0      = (const float*)d_in[0];
    const float* v0      = (const float*)d_in[1];
    const float* beta_p  = (const float*)d_in[2];
    const float* data_t  = (const float*)d_in[3];
    const float* t0_p    = (const float*)d_in[4];
    const float* tn_p    = (const float*)d_in[5];
    const int2*  data_uv = (const int2*)d_in[6];
    const int*   pair_u  = (const int*)d_in[7];
    const int*   pair_v  = (const int*)d_in[8];
    float* out = (float*)d_out;

    int n_points = in_sizes[0] / 2;
    int n_events = in_sizes[3];
    int n_pairs  = in_sizes[7];

    cvm_fused_kernel<<<NBLK, TPB>>>(z0, v0, beta_p, data_t, t0_p, tn_p,
                                    data_uv, pair_u, pair_v,
                                    n_points, n_events, n_pairs, out);
}